// round 15
// baseline (speedup 1.0000x reference)
#include <cuda_runtime.h>
#include <cuda_fp16.h>
#include <cstdint>

// Problem constants (fixed by the dataset)
#define NN   20000   // nodes
#define IND  256     // in_dim
#define OUTD 128     // out_dim
#define NS   8       // num sectors
#define NK   9       // K = S+1
#define NEP  40000   // edges per sector
#define EMAX 64      // per-(sector,src) edge-list capacity (Poisson(2) degrees)

// ---------------- scratch (device globals; no allocations allowed) ----------
__device__ __half d_H  [(size_t)NS * NN * OUTD];            // per-sector H fp16 (41MB)
__device__ __half d_zc [(size_t)NN * NK * OUTD];            // (z*in_norm) @ WC, fp16
__device__ __half d_zd [(size_t)NN * NK * OUTD];            // (z*in_norm) @ WD, fp16
// Both GEMMs plain fp16 (hi-only operands); error budget calibrated ~5e-4.
__device__ __half d_x2 [(size_t)NN * IND];                  // [N, 256] hi
__device__ __half d_z2 [(size_t)NN * NK * OUTD];            // [N*K, 128] hi
__device__ __half d_w1t[(size_t)NK * OUTD * IND];           // [9][128,256] transposed
__device__ __half d_w2t[(size_t)2  * OUTD * OUTD];          // [2][128,128] transposed
// CSR-ish fixed-capacity edge lists, rebuilt every call
__device__ int d_cnt [(size_t)NS * NN];
__device__ int d_eidx[(size_t)NS * NN * EMAX];

// ============================ PTX helpers ====================================
__device__ __forceinline__ uint32_t smem_u32(const void* p) {
    uint32_t a;
    asm("{ .reg .u64 t; cvta.to.shared.u64 t, %1; cvt.u32.u64 %0, t; }" : "=r"(a) : "l"(p));
    return a;
}
__device__ __forceinline__ void ldmx4(uint32_t* r, uint32_t addr) {
    asm volatile("ldmatrix.sync.aligned.m8n8.x4.shared.b16 {%0,%1,%2,%3}, [%4];"
        : "=r"(r[0]), "=r"(r[1]), "=r"(r[2]), "=r"(r[3]) : "r"(addr));
}
__device__ __forceinline__ void mma16816(float* c, const uint32_t* a, uint32_t b0, uint32_t b1) {
    asm volatile("mma.sync.aligned.m16n8k16.row.col.f32.f16.f16.f32 "
        "{%0,%1,%2,%3}, {%4,%5,%6,%7}, {%8,%9}, {%0,%1,%2,%3};"
        : "+f"(c[0]), "+f"(c[1]), "+f"(c[2]), "+f"(c[3])
        : "r"(a[0]), "r"(a[1]), "r"(a[2]), "r"(a[3]), "r"(b0), "r"(b1));
}
#define CP_ASYNC16(sp, gp) \
    asm volatile("cp.async.cg.shared.global [%0], [%1], 16;" :: "r"(sp), "l"(gp))
#define CP_COMMIT() asm volatile("cp.async.commit_group;" ::: "memory")
#define CP_WAIT1()  asm volatile("cp.async.wait_group 1;" ::: "memory")
#define CP_WAIT0()  asm volatile("cp.async.wait_group 0;" ::: "memory")

// ============================ conversion kernels =============================
// x fp32 [NN, IND] -> fp16 hi only; also zeroes cnt.
__global__ __launch_bounds__(256)
void conv_x(const float* __restrict__ in, __half* __restrict__ out,
            int* __restrict__ cnt)
{
    int i = blockIdx.x * blockDim.x + threadIdx.x;
    if (i < NS * NN) cnt[i] = 0;
    if (i >= NN * IND) return;
    out[i] = __float2half_rn(in[i]);
}

// weight conversions: b 0..8 -> w1t (transposed, K=IND); b 9..10 -> w2t
// (transposed, K=OUTD). All plain fp16.
__global__ __launch_bounds__(256)
void conv_w_all(const float* __restrict__ W_self, const float* __restrict__ W_sect,
                const float* __restrict__ WC, const float* __restrict__ WD,
                __half* __restrict__ w1t, __half* __restrict__ w2t)
{
    int b = blockIdx.y;
    int i = blockIdx.x * blockDim.x + threadIdx.x;
    if (b < 9) {
        const float* W = (b == 0) ? W_self : W_sect + (size_t)(b - 1) * IND * OUTD;
        __half* ob = w1t + (size_t)b * OUTD * IND;
        if (i >= IND * OUTD) return;
        int k = i / OUTD, n = i - k * OUTD;
        ob[(size_t)n * IND + k] = __float2half_rn(W[i]);
    } else {
        const float* W = (b == 9) ? WC : WD;
        __half* ob = w2t + (size_t)(b - 9) * OUTD * OUTD;
        if (i >= OUTD * OUTD) return;
        int k = i / OUTD, n = i - k * OUTD;
        ob[(size_t)n * OUTD + k] = __float2half_rn(W[i]);
    }
}

// ============================ shared GEMM pieces =============================
#define SROW 144                      // smem row pitch bytes (64 fp16 cols + pad)
#define ATILE (128 * SROW)            // 18432 B
#define SMEM_TOT (6 * ATILE)          // 110592 B (both GEMMs)

// warp-level MMA on one 64-col chunk: warp tile 64(M) x 32(N), 4 k16 steps.
__device__ __forceinline__ void chunk_mma(uint32_t sAb, uint32_t sBb,
                                          int warpM, int warpN, int lane,
                                          float acc[4][4][4])
{
    #pragma unroll
    for (int ks = 0; ks < 4; ++ks) {
        const uint32_t colOff = (ks * 16 + (lane >> 4) * 8) * 2;
        uint32_t a[4][4];
        #pragma unroll
        for (int mt = 0; mt < 4; ++mt)
            ldmx4(a[mt], sAb + (warpM * 64 + mt * 16 + (lane & 15)) * SROW + colOff);
        uint32_t b[2][4];
        #pragma unroll
        for (int nt2 = 0; nt2 < 2; ++nt2)
            ldmx4(b[nt2], sBb + (warpN * 32 + nt2 * 16 + (lane & 15)) * SROW + colOff);
        #pragma unroll
        for (int mt = 0; mt < 4; ++mt)
            #pragma unroll
            for (int nt2 = 0; nt2 < 2; ++nt2) {
                mma16816(acc[mt][nt2 * 2 + 0], a[mt], b[nt2][0], b[nt2][2]);
                mma16816(acc[mt][nt2 * 2 + 1], a[mt], b[nt2][1], b[nt2][3]);
            }
    }
}

// ============================ GEMM 1: branch GEMM ============================
// C[M,128] = x_hi[M,256] @ w_hi[128,256]^T, plain fp16. 256 thr, 8 warps 2x4.
// B persistent in smem (4 k-chunks, 64KB); A streams through 2 buffers.
// grid (tiles, 9). branch 0 -> z2 slice 0 (fp16 hi); 1..8 -> H fp16 * out_norm.
__global__ __launch_bounds__(256, 2)
void mma_gemm1(const __half* __restrict__ A2, const __half* __restrict__ Bbase,
               __half* __restrict__ z2out, __half* __restrict__ Hout,
               const float* __restrict__ out_norm)
{
    extern __shared__ __align__(16) char smem[];
    char* sB = smem;                    // B chunks [0..3]
    char* sA = smem + 4 * ATILE;        // A buffers [0..1]

    const int tid = threadIdx.x;
    const int wid = tid >> 5, lane = tid & 31;
    const int warpM = wid & 1, warpN = wid >> 1;
    const int branch = blockIdx.y;
    const int rowBase = blockIdx.x * 128;
    const int lda = IND;                // 256
    const __half* B2 = Bbase + (size_t)branch * OUTD * lda;
    const uint32_t sB_u = smem_u32(sB);
    const uint32_t sA_u = smem_u32(sA);
    float acc[4][4][4] = {};

    auto loadA = [&](int c, int buf) {
        char* dst = sA + buf * ATILE;
        int k0 = c * 64;
        #pragma unroll
        for (int i = 0; i < 4; ++i) {
            int idx = tid + i * 256;
            int r = idx >> 3, c16 = idx & 7;
            int grow = rowBase + r; if (grow > NN - 1) grow = NN - 1;
            CP_ASYNC16(smem_u32(dst + r * SROW + c16 * 16),
                       A2 + (size_t)grow * lda + k0 + c16 * 8);
        }
    };

    // persistent B: 4 chunk-tiles
    #pragma unroll
    for (int ch = 0; ch < 4; ++ch) {
        char* dst = sB + ch * ATILE;
        #pragma unroll
        for (int i = 0; i < 4; ++i) {
            int idx = tid + i * 256;
            int r = idx >> 3, c16 = idx & 7;
            CP_ASYNC16(smem_u32(dst + r * SROW + c16 * 16),
                       B2 + (size_t)r * lda + ch * 64 + c16 * 8);
        }
    }
    loadA(0, 0); CP_COMMIT();           // G0 = B + A0
    loadA(1, 1); CP_COMMIT();           // G1 = A1

    #pragma unroll
    for (int c = 0; c < 4; ++c) {
        if (c + 1 < 4) CP_WAIT1(); else CP_WAIT0();
        __syncthreads();                // A[c%2] + (c==0: all B) ready
        chunk_mma(sA_u + (c & 1) * ATILE, sB_u + c * ATILE, warpM, warpN, lane, acc);
        if (c + 2 < 4) {
            __syncthreads();            // everyone done with buffer (c%2)
            loadA(c + 2, c & 1); CP_COMMIT();
        }
    }

    const int g = lane >> 2, t4 = lane & 3;
    #pragma unroll
    for (int mt = 0; mt < 4; ++mt) {
        int row0 = rowBase + warpM * 64 + mt * 16 + g;
        int row1 = row0 + 8;
        if (branch == 0) {
            #pragma unroll
            for (int nt = 0; nt < 4; ++nt) {
                int col = warpN * 32 + nt * 8 + 2 * t4;
                if (row0 < NN) {
                    __half2 v = __floats2half2_rn(acc[mt][nt][0], acc[mt][nt][1]);
                    *reinterpret_cast<__half2*>(z2out + (size_t)row0 * NK * OUTD + col) = v;
                }
                if (row1 < NN) {
                    __half2 v = __floats2half2_rn(acc[mt][nt][2], acc[mt][nt][3]);
                    *reinterpret_cast<__half2*>(z2out + (size_t)row1 * NK * OUTD + col) = v;
                }
            }
        } else {
            __half* C = Hout + (size_t)(branch - 1) * NN * OUTD;
            float s0 = (row0 < NN) ? out_norm[row0] : 0.f;
            float s1 = (row1 < NN) ? out_norm[row1] : 0.f;
            #pragma unroll
            for (int nt = 0; nt < 4; ++nt) {
                int col = warpN * 32 + nt * 8 + 2 * t4;
                if (row0 < NN) {
                    __half2 v = __floats2half2_rn(acc[mt][nt][0] * s0, acc[mt][nt][1] * s0);
                    *reinterpret_cast<__half2*>(C + (size_t)row0 * OUTD + col) = v;
                }
                if (row1 < NN) {
                    __half2 v = __floats2half2_rn(acc[mt][nt][2] * s1, acc[mt][nt][3] * s1);
                    *reinterpret_cast<__half2*>(C + (size_t)row1 * OUTD + col) = v;
                }
            }
        }
    }
}

// ============================ GEMM 2: fused WC+WD ============================
// One CTA computes BOTH zc and zd for its 128 rows: logical N=256 via
// B = [WC^T ; WD^T]. 512 thr, 16 warps (2m x 8n), warp tile 64x32.
// A (z2) read ONCE. All operands loaded in one cp.async group (K small).
#define M2 (NN * NK)
__global__ __launch_bounds__(512, 1)
void mma_gemm2(const __half* __restrict__ A2, const __half* __restrict__ Bbase,
               __half* __restrict__ zc, __half* __restrict__ zd,
               const float* __restrict__ in_norm)
{
    extern __shared__ __align__(16) char smem[];
    char* sB = smem;                    // B chunks: [WC k0, WC k1, WD k0, WD k1]
    char* sA = smem + 4 * ATILE;        // A chunks [k0, k1]

    const int tid = threadIdx.x;
    const int wid = tid >> 5, lane = tid & 31;
    const int warpM = wid & 1;          // 0..1 -> 64-row half
    const int warpN = wid >> 1;         // 0..7 -> 32-col slice of 256
    const int brW   = warpN >> 2;       // 0 = zc, 1 = zd
    const int nLoc  = warpN & 3;        // 32-col slice within branch
    const int rowBase = blockIdx.x * 128;
    const int lda = OUTD;               // 128
    const uint32_t sB_u = smem_u32(sB);
    const uint32_t sA_u = smem_u32(sA);
    float acc[4][4][4] = {};

    // load B: 4 chunks (branch bh, k-chunk kc); 1024 segs each, 2 iters @512thr
    #pragma unroll
    for (int ch = 0; ch < 4; ++ch) {
        int bh = ch >> 1, kc = ch & 1;
        const __half* Bsrc = Bbase + (size_t)bh * OUTD * OUTD;
        char* dst = sB + ch * ATILE;
        #pragma unroll
        for (int i = 0; i < 2; ++i) {
            int idx = tid + i * 512;
            int r = idx >> 3, c16 = idx & 7;
            CP_ASYNC16(smem_u32(dst + r * SROW + c16 * 16),
                       Bsrc + (size_t)r * lda + kc * 64 + c16 * 8);
        }
    }
    // load A: 2 k-chunks
    #pragma unroll
    for (int kc = 0; kc < 2; ++kc) {
        char* dst = sA + kc * ATILE;
        #pragma unroll
        for (int i = 0; i < 2; ++i) {
            int idx = tid + i * 512;
            int r = idx >> 3, c16 = idx & 7;
            int grow = rowBase + r; if (grow > M2 - 1) grow = M2 - 1;
            CP_ASYNC16(smem_u32(dst + r * SROW + c16 * 16),
                       A2 + (size_t)grow * lda + kc * 64 + c16 * 8);
        }
    }
    CP_COMMIT();
    CP_WAIT0();
    __syncthreads();

    #pragma unroll
    for (int c = 0; c < 2; ++c)
        chunk_mma(sA_u + c * ATILE, sB_u + (brW * 2 + c) * ATILE,
                  warpM, nLoc, lane, acc);

    __half* C = brW ? zd : zc;
    const int g = lane >> 2, t4 = lane & 3;
    #pragma unroll
    for (int mt = 0; mt < 4; ++mt) {
        int row0 = rowBase + warpM * 64 + mt * 16 + g;
        int row1 = row0 + 8;
        float s0 = (row0 < M2) ? in_norm[row0 / NK] : 0.f;
        float s1 = (row1 < M2) ? in_norm[row1 / NK] : 0.f;
        #pragma unroll
        for (int nt = 0; nt < 4; ++nt) {
            int col = nLoc * 32 + nt * 8 + 2 * t4;
            if (row0 < M2) {
                __half2 v = __floats2half2_rn(acc[mt][nt][0] * s0, acc[mt][nt][1] * s0);
                *reinterpret_cast<__half2*>(C + (size_t)row0 * OUTD + col) = v;
            }
            if (row1 < M2) {
                __half2 v = __floats2half2_rn(acc[mt][nt][2] * s1, acc[mt][nt][3] * s1);
                *reinterpret_cast<__half2*>(C + (size_t)row1 * OUTD + col) = v;
            }
        }
    }
}

// ---------------- edge-list build: bucket (sector,src) <- dst ----------------
__global__ __launch_bounds__(256)
void build_lists(const int* __restrict__ rows, const int* __restrict__ cols,
                 int* __restrict__ cnt, int* __restrict__ eidx)
{
    int i = blockIdx.x * blockDim.x + threadIdx.x;
    if (i >= NS * NEP) return;
    int s = i / NEP;
    int src = rows[i];
    int dst = cols[i];
    int b = s * NN + src;
    int slot = atomicAdd(&cnt[b], 1);
    if (slot < EMAX) eidx[(size_t)b * EMAX + slot] = dst;
}

// ---------------- gather aggregation: one warp per (sector,src) --------------
// acc = sum(fp16 H rows) in fp32 (unroll-2, MLP=2); write z2 slice fp16 hi.
__global__ __launch_bounds__(256)
void gather_agg(const int* __restrict__ cnt, const int* __restrict__ eidx,
                const __half* __restrict__ H, __half* __restrict__ z2)
{
    int gw   = (blockIdx.x * blockDim.x + threadIdx.x) >> 5;
    int lane = threadIdx.x & 31;
    if (gw >= NS * NN) return;
    int s = gw / NN, src = gw - s * NN;
    int c = cnt[gw]; if (c > EMAX) c = EMAX;
    const int* lst = eidx + (size_t)gw * EMAX;
    const __half* Hs = H + (size_t)s * NN * OUTD;

    float4 acc0 = make_float4(0.f, 0.f, 0.f, 0.f);
    float4 acc1 = make_float4(0.f, 0.f, 0.f, 0.f);
    int i = 0;
    for (; i + 1 < c; i += 2) {
        const __half2* p0 = reinterpret_cast<const __half2*>(Hs + (size_t)lst[i]     * OUTD) + lane * 2;
        const __half2* p1 = reinterpret_cast<const __half2*>(Hs + (size_t)lst[i + 1] * OUTD) + lane * 2;
        __half2 a01 = p0[0], a23 = p0[1];
        __half2 b01 = p1[0], b23 = p1[1];
        acc0.x += __half2float(a01.x); acc0.y += __half2float(a01.y);
        acc0.z += __half2float(a23.x); acc0.w += __half2float(a23.y);
        acc1.x += __half2float(b01.x); acc1.y += __half2float(b01.y);
        acc1.z += __half2float(b23.x); acc1.w += __half2float(b23.y);
    }
    if (i < c) {
        const __half2* p0 = reinterpret_cast<const __half2*>(Hs + (size_t)lst[i] * OUTD) + lane * 2;
        __half2 a01 = p0[0], a23 = p0[1];
        acc0.x += __half2float(a01.x); acc0.y += __half2float(a01.y);
        acc0.z += __half2float(a23.x); acc0.w += __half2float(a23.y);
    }
    acc0.x += acc1.x; acc0.y += acc1.y; acc0.z += acc1.z; acc0.w += acc1.w;

    __half* zp = z2 + ((size_t)src * NK + 1 + s) * OUTD;
    *reinterpret_cast<__half2*>(zp + lane * 4 + 0) = __floats2half2_rn(acc0.x, acc0.y);
    *reinterpret_cast<__half2*>(zp + lane * 4 + 2) = __floats2half2_rn(acc0.z, acc0.w);
}

// ---------------- per-node interaction: one warp per node, register-resident -
__global__ __launch_bounds__(128)
void interact(const __half* __restrict__ zc, const __half* __restrict__ zd,
              const float* __restrict__ gw, const float* __restrict__ gb,
              float* __restrict__ out)
{
    __shared__ float gcs[4][NK][NK];
    __shared__ float gds[4][NK][NK];
    const int w = threadIdx.x >> 5;
    const int lane = threadIdx.x & 31;
    const int n = blockIdx.x * 4 + w;          // NN = 5000*4

    const __half2* zcn = reinterpret_cast<const __half2*>(zc + (size_t)n * NK * OUTD);
    const __half2* zdn = reinterpret_cast<const __half2*>(zd + (size_t)n * NK * OUTD);

    float a[NK][4], b[NK][4];
    #pragma unroll
    for (int r = 0; r < NK; ++r) {
        __half2 c0 = zcn[r * 64 + lane];
        __half2 c1 = zcn[r * 64 + 32 + lane];
        a[r][0] = __half2float(c0.x); a[r][1] = __half2float(c0.y);
        a[r][2] = __half2float(c1.x); a[r][3] = __half2float(c1.y);
        __half2 d0 = zdn[r * 64 + lane];
        __half2 d1 = zdn[r * 64 + 32 + lane];
        b[r][0] = __half2float(d0.x); b[r][1] = __half2float(d0.y);
        b[r][2] = __half2float(d1.x); b[r][3] = __half2float(d1.y);
    }

    #pragma unroll
    for (int k = 0; k < NK; ++k) {
        #pragma unroll
        for (int j = k; j < NK; ++j) {
            float pc = a[k][0]*a[j][0] + a[k][1]*a[j][1] + a[k][2]*a[j][2] + a[k][3]*a[j][3];
            float pd = b[k][0]*b[j][0] + b[k][1]*b[j][1] + b[k][2]*b[j][2] + b[k][3]*b[j][3];
            #pragma unroll
            for (int off = 16; off; off >>= 1) {
                pc += __shfl_xor_sync(0xffffffffu, pc, off);
                pd += __shfl_xor_sync(0xffffffffu, pd, off);
            }
            if (lane == 0) {
                gcs[w][k][j] = pc; gcs[w][j][k] = pc;
                gds[w][k][j] = pd; gds[w][j][k] = pd;
            }
        }
    }
    __syncwarp();

    if (lane < NK) {
        float row[NK]; float m = -1e30f;
        #pragma unroll
        for (int j = 0; j < NK; ++j) { row[j] = gcs[w][lane][j]; m = fmaxf(m, row[j]); }
        float ssum = 0.f;
        #pragma unroll
        for (int j = 0; j < NK; ++j) { row[j] = expf(row[j] - m); ssum += row[j]; }
        float inv = 1.f / ssum;
        #pragma unroll
        for (int j = 0; j < NK; ++j) gcs[w][lane][j] = row[j] * inv;
    } else if (lane >= 16 && lane < 16 + NK) {
        int k = lane - 16;
        float q = gds[w][k][k];
        float row[NK]; float m = -1e30f;
        #pragma unroll
        for (int j = 0; j < NK; ++j) { row[j] = q - gds[w][k][j]; m = fmaxf(m, row[j]); }
        float ssum = 0.f;
        #pragma unroll
        for (int j = 0; j < NK; ++j) { row[j] = expf(row[j] - m); ssum += row[j]; }
        float inv = 1.f / ssum;
        #pragma unroll
        for (int j = 0; j < NK; ++j) gds[w][k][j] = row[j] * inv;
    }
    __syncwarp();

    float com[NK][4], dis[NK][4];
    float gp = 0.f;
    #pragma unroll
    for (int k = 0; k < NK; ++k) {
        float ck0 = 0.f, ck1 = 0.f, ck2 = 0.f, ck3 = 0.f;
        float dk0 = 0.f, dk1 = 0.f, dk2 = 0.f, dk3 = 0.f;
        #pragma unroll
        for (int j = 0; j < NK; ++j) {
            float acv = gcs[w][k][j], adv = gds[w][k][j];
            ck0 += acv * a[j][0]; ck1 += acv * a[j][1];
            ck2 += acv * a[j][2]; ck3 += acv * a[j][3];
            dk0 += adv * b[j][0]; dk1 += adv * b[j][1];
            dk2 += adv * b[j][2]; dk3 += adv * b[j][3];
        }
        dk0 = b[k][0] - dk0; dk1 = b[k][1] - dk1;
        dk2 = b[k][2] - dk2; dk3 = b[k][3] - dk3;
        com[k][0] = ck0; com[k][1] = ck1; com[k][2] = ck2; com[k][3] = ck3;
        dis[k][0] = dk0; dis[k][1] = dk1; dis[k][2] = dk2; dis[k][3] = dk3;

        const float2 gc0 = *reinterpret_cast<const float2*>(gw + k * OUTD + 2 * lane);
        const float2 gc1 = *reinterpret_cast<const float2*>(gw + k * OUTD + 64 + 2 * lane);
        const float2 gd0 = *reinterpret_cast<const float2*>(gw + NK * OUTD + k * OUTD + 2 * lane);
        const float2 gd1 = *reinterpret_cast<const float2*>(gw + NK * OUTD + k * OUTD + 64 + 2 * lane);
        gp += ck0 * gc0.x + ck1 * gc0.y + ck2 * gc1.x + ck3 * gc1.y
            + dk0 * gd0.x + dk1 * gd0.y + dk2 * gd1.x + dk3 * gd1.y;
    }
    #pragma unroll
    for (int off = 16; off; off >>= 1)
        gp += __shfl_xor_sync(0xffffffffu, gp, off);
    const float beta = 1.f / (1.f + expf(-(gp + gb[0])));

    float* op = out + (size_t)n * (NK * OUTD);
    #pragma unroll
    for (int k = 0; k < NK; ++k) {
        float2 v0 = make_float2(beta * com[k][0] + (1.f - beta) * dis[k][0],
                                beta * com[k][1] + (1.f - beta) * dis[k][1]);
        float2 v1 = make_float2(beta * com[k][2] + (1.f - beta) * dis[k][2],
                                beta * com[k][3] + (1.f - beta) * dis[k][3]);
        *reinterpret_cast<float2*>(op + k * OUTD + 2 * lane) = v0;
        *reinterpret_cast<float2*>(op + k * OUTD + 64 + 2 * lane) = v1;
    }
}

// ---------------- launch ------------------------------------------------------
extern "C" void kernel_launch(void* const* d_in, const int* in_sizes, int n_in,
                              void* d_out, int out_size)
{
    const float* x        = (const float*)d_in[0];
    const float* W_self   = (const float*)d_in[1];
    const float* W_sect   = (const float*)d_in[2];
    const float* WC       = (const float*)d_in[3];
    const float* WD       = (const float*)d_in[4];
    const float* gate_w   = (const float*)d_in[5];
    const float* gate_b   = (const float*)d_in[6];
    const float* out_norm = (const float*)d_in[7];
    const float* in_norm  = (const float*)d_in[8];
    const int*   rows     = (const int*)d_in[9];
    const int*   cols     = (const int*)d_in[10];
    float* out = (float*)d_out;

    __half *H, *zc, *zd, *x2, *z2, *w1t, *w2t;
    int *cnt, *eidx;
    cudaGetSymbolAddress((void**)&H,    d_H);
    cudaGetSymbolAddress((void**)&zc,   d_zc);
    cudaGetSymbolAddress((void**)&zd,   d_zd);
    cudaGetSymbolAddress((void**)&x2,   d_x2);
    cudaGetSymbolAddress((void**)&z2,   d_z2);
    cudaGetSymbolAddress((void**)&w1t,  d_w1t);
    cudaGetSymbolAddress((void**)&w2t,  d_w2t);
    cudaGetSymbolAddress((void**)&cnt,  d_cnt);
    cudaGetSymbolAddress((void**)&eidx, d_eidx);

    cudaFuncSetAttribute(mma_gemm1, cudaFuncAttributeMaxDynamicSharedMemorySize, SMEM_TOT);
    cudaFuncSetAttribute(mma_gemm2, cudaFuncAttributeMaxDynamicSharedMemorySize, SMEM_TOT);

    // (0) convert x -> fp16 hi; also zeroes the bucket counters
    conv_x<<<(NN * IND + 255) / 256, 256>>>(x, x2, cnt);

    // (1) build per-(sector,src) edge lists
    build_lists<<<(NS * NEP + 255) / 256, 256>>>(rows, cols, cnt, eidx);

    // (2) weight conversions, right-sized grid (128 x 11 blocks)
    conv_w_all<<<dim3((IND * OUTD + 255) / 256, 11), 256>>>(W_self, W_sect, WC, WD, w1t, w2t);

    // (3) branch GEMMs, plain fp16, persistent-B   [profiled slot]
    mma_gemm1<<<dim3((NN + 127) / 128, NK), 256, SMEM_TOT>>>(
        x2, w1t, z2, H, out_norm);

    // (4) gather aggregation -> z2 slices 1..8 (fp16 hi, MLP=2)
    gather_agg<<<(NS * NN * 32 + 255) / 256, 256>>>(cnt, eidx, H, z2);

    // (5) fused WC+WD GEMM: one CTA -> both zc and zd (A read once)
    mma_gemm2<<<(M2 + 127) / 128, 512, SMEM_TOT>>>(
        z2, w2t, zc, zd, in_norm);

    // (6) per-node interaction + gate, warp-per-node register-resident
    interact<<<NN / 4, 128>>>(zc, zd, gate_w, gate_b, out);
}

// round 16
// speedup vs baseline: 1.0632x; 1.0632x over previous
#include <cuda_runtime.h>
#include <cuda_fp16.h>
#include <cstdint>

// Problem constants (fixed by the dataset)
#define NN   20000   // nodes
#define IND  256     // in_dim
#define OUTD 128     // out_dim
#define NS   8       // num sectors
#define NK   9       // K = S+1
#define NEP  40000   // edges per sector
#define EMAX 64      // per-(sector,src) edge-list capacity (Poisson(2) degrees)

// ---------------- scratch (device globals; no allocations allowed) ----------
__device__ __half d_H  [(size_t)NS * NN * OUTD];            // per-sector H fp16 (41MB)
__device__ __half d_zc [(size_t)NN * NK * OUTD];            // (z*in_norm) @ WC, fp16
__device__ __half d_zd [(size_t)NN * NK * OUTD];            // (z*in_norm) @ WD, fp16
// Both GEMMs plain fp16 (hi-only operands); error budget calibrated ~5e-4.
__device__ __half d_x2 [(size_t)NN * IND];                  // [N, 256] hi
__device__ __half d_z2 [(size_t)NN * NK * OUTD];            // [N*K, 128] hi
__device__ __half d_w1t[(size_t)NK * OUTD * IND];           // [9][128,256] transposed
__device__ __half d_w2t[(size_t)2  * OUTD * OUTD];          // [2][128,128] transposed
// CSR-ish fixed-capacity edge lists, rebuilt every call
__device__ int d_cnt [(size_t)NS * NN];
__device__ int d_eidx[(size_t)NS * NN * EMAX];

// ============================ PTX helpers ====================================
__device__ __forceinline__ uint32_t smem_u32(const void* p) {
    uint32_t a;
    asm("{ .reg .u64 t; cvta.to.shared.u64 t, %1; cvt.u32.u64 %0, t; }" : "=r"(a) : "l"(p));
    return a;
}
__device__ __forceinline__ void ldmx4(uint32_t* r, uint32_t addr) {
    asm volatile("ldmatrix.sync.aligned.m8n8.x4.shared.b16 {%0,%1,%2,%3}, [%4];"
        : "=r"(r[0]), "=r"(r[1]), "=r"(r[2]), "=r"(r[3]) : "r"(addr));
}
__device__ __forceinline__ void mma16816(float* c, const uint32_t* a, uint32_t b0, uint32_t b1) {
    asm volatile("mma.sync.aligned.m16n8k16.row.col.f32.f16.f16.f32 "
        "{%0,%1,%2,%3}, {%4,%5,%6,%7}, {%8,%9}, {%0,%1,%2,%3};"
        : "+f"(c[0]), "+f"(c[1]), "+f"(c[2]), "+f"(c[3])
        : "r"(a[0]), "r"(a[1]), "r"(a[2]), "r"(a[3]), "r"(b0), "r"(b1));
}
#define CP_ASYNC16(sp, gp) \
    asm volatile("cp.async.cg.shared.global [%0], [%1], 16;" :: "r"(sp), "l"(gp))
#define CP_COMMIT() asm volatile("cp.async.commit_group;" ::: "memory")
#define CP_WAIT1()  asm volatile("cp.async.wait_group 1;" ::: "memory")
#define CP_WAIT0()  asm volatile("cp.async.wait_group 0;" ::: "memory")

// ============================ conversion kernels =============================
// x fp32 [NN, IND] -> fp16 hi only; also zeroes cnt.
__global__ __launch_bounds__(256)
void conv_x(const float* __restrict__ in, __half* __restrict__ out,
            int* __restrict__ cnt)
{
    int i = blockIdx.x * blockDim.x + threadIdx.x;
    if (i < NS * NN) cnt[i] = 0;
    if (i >= NN * IND) return;
    out[i] = __float2half_rn(in[i]);
}

// weight conversions: b 0..8 -> w1t (transposed, K=IND); b 9..10 -> w2t
// (transposed, K=OUTD). All plain fp16.
__global__ __launch_bounds__(256)
void conv_w_all(const float* __restrict__ W_self, const float* __restrict__ W_sect,
                const float* __restrict__ WC, const float* __restrict__ WD,
                __half* __restrict__ w1t, __half* __restrict__ w2t)
{
    int b = blockIdx.y;
    int i = blockIdx.x * blockDim.x + threadIdx.x;
    if (b < 9) {
        const float* W = (b == 0) ? W_self : W_sect + (size_t)(b - 1) * IND * OUTD;
        __half* ob = w1t + (size_t)b * OUTD * IND;
        if (i >= IND * OUTD) return;
        int k = i / OUTD, n = i - k * OUTD;
        ob[(size_t)n * IND + k] = __float2half_rn(W[i]);
    } else {
        const float* W = (b == 9) ? WC : WD;
        __half* ob = w2t + (size_t)(b - 9) * OUTD * OUTD;
        if (i >= OUTD * OUTD) return;
        int k = i / OUTD, n = i - k * OUTD;
        ob[(size_t)n * OUTD + k] = __float2half_rn(W[i]);
    }
}

// ============================ shared GEMM pieces =============================
#define SROW 144                      // smem row pitch bytes (64 fp16 cols + pad)
#define ATILE (128 * SROW)            // 18432 B
#define SMEM_G1 (6 * ATILE)           // mma1: 4 B-chunks + 2 A-buffers
#define SMEM_G2 (4 * ATILE)           // mma2: 2 B-chunks + 2 A-buffers

// warp-level MMA on one 64-col chunk: warp tile 64(M) x 32(N), 4 k16 steps.
__device__ __forceinline__ void chunk_mma(uint32_t sAb, uint32_t sBb,
                                          int warpM, int warpN, int lane,
                                          float acc[4][4][4])
{
    #pragma unroll
    for (int ks = 0; ks < 4; ++ks) {
        const uint32_t colOff = (ks * 16 + (lane >> 4) * 8) * 2;
        uint32_t a[4][4];
        #pragma unroll
        for (int mt = 0; mt < 4; ++mt)
            ldmx4(a[mt], sAb + (warpM * 64 + mt * 16 + (lane & 15)) * SROW + colOff);
        uint32_t b[2][4];
        #pragma unroll
        for (int nt2 = 0; nt2 < 2; ++nt2)
            ldmx4(b[nt2], sBb + (warpN * 32 + nt2 * 16 + (lane & 15)) * SROW + colOff);
        #pragma unroll
        for (int mt = 0; mt < 4; ++mt)
            #pragma unroll
            for (int nt2 = 0; nt2 < 2; ++nt2) {
                mma16816(acc[mt][nt2 * 2 + 0], a[mt], b[nt2][0], b[nt2][2]);
                mma16816(acc[mt][nt2 * 2 + 1], a[mt], b[nt2][1], b[nt2][3]);
            }
    }
}

// ============================ GEMM 1: branch GEMM ============================
// C[M,128] = x_hi[M,256] @ w_hi[128,256]^T, plain fp16. 256 thr, 8 warps 2x4.
// B persistent in smem (4 k-chunks, 64KB); A streams through 2 buffers.
// grid (tiles, 9). branch 0 -> z2 slice 0 (fp16 hi); 1..8 -> H fp16 * out_norm.
__global__ __launch_bounds__(256, 2)
void mma_gemm1(const __half* __restrict__ A2, const __half* __restrict__ Bbase,
               __half* __restrict__ z2out, __half* __restrict__ Hout,
               const float* __restrict__ out_norm)
{
    extern __shared__ __align__(16) char smem[];
    char* sB = smem;                    // B chunks [0..3]
    char* sA = smem + 4 * ATILE;        // A buffers [0..1]

    const int tid = threadIdx.x;
    const int wid = tid >> 5, lane = tid & 31;
    const int warpM = wid & 1, warpN = wid >> 1;
    const int branch = blockIdx.y;
    const int rowBase = blockIdx.x * 128;
    const int lda = IND;                // 256
    const __half* B2 = Bbase + (size_t)branch * OUTD * lda;
    const uint32_t sB_u = smem_u32(sB);
    const uint32_t sA_u = smem_u32(sA);
    float acc[4][4][4] = {};

    auto loadA = [&](int c, int buf) {
        char* dst = sA + buf * ATILE;
        int k0 = c * 64;
        #pragma unroll
        for (int i = 0; i < 4; ++i) {
            int idx = tid + i * 256;
            int r = idx >> 3, c16 = idx & 7;
            int grow = rowBase + r; if (grow > NN - 1) grow = NN - 1;
            CP_ASYNC16(smem_u32(dst + r * SROW + c16 * 16),
                       A2 + (size_t)grow * lda + k0 + c16 * 8);
        }
    };

    // persistent B: 4 chunk-tiles
    #pragma unroll
    for (int ch = 0; ch < 4; ++ch) {
        char* dst = sB + ch * ATILE;
        #pragma unroll
        for (int i = 0; i < 4; ++i) {
            int idx = tid + i * 256;
            int r = idx >> 3, c16 = idx & 7;
            CP_ASYNC16(smem_u32(dst + r * SROW + c16 * 16),
                       B2 + (size_t)r * lda + ch * 64 + c16 * 8);
        }
    }
    loadA(0, 0); CP_COMMIT();           // G0 = B + A0
    loadA(1, 1); CP_COMMIT();           // G1 = A1

    #pragma unroll
    for (int c = 0; c < 4; ++c) {
        if (c + 1 < 4) CP_WAIT1(); else CP_WAIT0();
        __syncthreads();                // A[c%2] + (c==0: all B) ready
        chunk_mma(sA_u + (c & 1) * ATILE, sB_u + c * ATILE, warpM, warpN, lane, acc);
        if (c + 2 < 4) {
            __syncthreads();            // everyone done with buffer (c%2)
            loadA(c + 2, c & 1); CP_COMMIT();
        }
    }

    const int g = lane >> 2, t4 = lane & 3;
    #pragma unroll
    for (int mt = 0; mt < 4; ++mt) {
        int row0 = rowBase + warpM * 64 + mt * 16 + g;
        int row1 = row0 + 8;
        if (branch == 0) {
            #pragma unroll
            for (int nt = 0; nt < 4; ++nt) {
                int col = warpN * 32 + nt * 8 + 2 * t4;
                if (row0 < NN) {
                    __half2 v = __floats2half2_rn(acc[mt][nt][0], acc[mt][nt][1]);
                    *reinterpret_cast<__half2*>(z2out + (size_t)row0 * NK * OUTD + col) = v;
                }
                if (row1 < NN) {
                    __half2 v = __floats2half2_rn(acc[mt][nt][2], acc[mt][nt][3]);
                    *reinterpret_cast<__half2*>(z2out + (size_t)row1 * NK * OUTD + col) = v;
                }
            }
        } else {
            __half* C = Hout + (size_t)(branch - 1) * NN * OUTD;
            float s0 = (row0 < NN) ? out_norm[row0] : 0.f;
            float s1 = (row1 < NN) ? out_norm[row1] : 0.f;
            #pragma unroll
            for (int nt = 0; nt < 4; ++nt) {
                int col = warpN * 32 + nt * 8 + 2 * t4;
                if (row0 < NN) {
                    __half2 v = __floats2half2_rn(acc[mt][nt][0] * s0, acc[mt][nt][1] * s0);
                    *reinterpret_cast<__half2*>(C + (size_t)row0 * OUTD + col) = v;
                }
                if (row1 < NN) {
                    __half2 v = __floats2half2_rn(acc[mt][nt][2] * s1, acc[mt][nt][3] * s1);
                    *reinterpret_cast<__half2*>(C + (size_t)row1 * OUTD + col) = v;
                }
            }
        }
    }
}

// ============================ GEMM 2: WC/WD, persistent B ===================
// C[M,128] = z2[M,128] @ w2t[128,128]^T * in_norm[row/9], output fp16.
// B persistent in smem (2 chunks); A chunks stream (2 buffers). Kd = 128.
// (round-14 proven version; occ 2, pipelined)
#define M2 (NN * NK)
__global__ __launch_bounds__(256, 2)
void mma_gemm2(const __half* __restrict__ A2, const __half* __restrict__ Bbase,
               __half* __restrict__ zc, __half* __restrict__ zd,
               const float* __restrict__ in_norm)
{
    extern __shared__ __align__(16) char smem[];
    char* sB = smem;                    // B chunks [0..1]
    char* sA = smem + 2 * ATILE;        // A buffers [0..1]

    const int tid = threadIdx.x;
    const int wid = tid >> 5, lane = tid & 31;
    const int warpM = wid & 1, warpN = wid >> 1;
    const int branch = blockIdx.x & 1;
    const int rowBase = (blockIdx.x >> 1) * 128;
    const int lda = OUTD;               // 128
    const __half* B2 = Bbase + (size_t)branch * OUTD * lda;
    __half* C = branch ? zd : zc;
    const uint32_t sB_u = smem_u32(sB);
    const uint32_t sA_u = smem_u32(sA);
    float acc[4][4][4] = {};

    auto loadA = [&](int c, int buf) {
        char* dst = sA + buf * ATILE;
        int k0 = c * 64;
        #pragma unroll
        for (int i = 0; i < 4; ++i) {
            int idx = tid + i * 256;
            int r = idx >> 3, c16 = idx & 7;
            int grow = rowBase + r; if (grow > M2 - 1) grow = M2 - 1;
            CP_ASYNC16(smem_u32(dst + r * SROW + c16 * 16),
                       A2 + (size_t)grow * lda + k0 + c16 * 8);
        }
    };

    // persistent B: 2 chunk-tiles
    #pragma unroll
    for (int ch = 0; ch < 2; ++ch) {
        char* dst = sB + ch * ATILE;
        #pragma unroll
        for (int i = 0; i < 4; ++i) {
            int idx = tid + i * 256;
            int r = idx >> 3, c16 = idx & 7;
            CP_ASYNC16(smem_u32(dst + r * SROW + c16 * 16),
                       B2 + (size_t)r * lda + ch * 64 + c16 * 8);
        }
    }
    loadA(0, 0); CP_COMMIT();           // G0 = B + A0
    loadA(1, 1); CP_COMMIT();           // G1 = A1

    #pragma unroll
    for (int c = 0; c < 2; ++c) {
        if (c == 0) CP_WAIT1(); else CP_WAIT0();
        __syncthreads();
        chunk_mma(sA_u + c * ATILE, sB_u + c * ATILE, warpM, warpN, lane, acc);
    }

    const int g = lane >> 2, t4 = lane & 3;
    #pragma unroll
    for (int mt = 0; mt < 4; ++mt) {
        int row0 = rowBase + warpM * 64 + mt * 16 + g;
        int row1 = row0 + 8;
        float s0 = (row0 < M2) ? in_norm[row0 / NK] : 0.f;
        float s1 = (row1 < M2) ? in_norm[row1 / NK] : 0.f;
        #pragma unroll
        for (int nt = 0; nt < 4; ++nt) {
            int col = warpN * 32 + nt * 8 + 2 * t4;
            if (row0 < M2) {
                __half2 v = __floats2half2_rn(acc[mt][nt][0] * s0, acc[mt][nt][1] * s0);
                *reinterpret_cast<__half2*>(C + (size_t)row0 * OUTD + col) = v;
            }
            if (row1 < M2) {
                __half2 v = __floats2half2_rn(acc[mt][nt][2] * s1, acc[mt][nt][3] * s1);
                *reinterpret_cast<__half2*>(C + (size_t)row1 * OUTD + col) = v;
            }
        }
    }
}

// ---------------- edge-list build: bucket (sector,src) <- dst ----------------
__global__ __launch_bounds__(256)
void build_lists(const int* __restrict__ rows, const int* __restrict__ cols,
                 int* __restrict__ cnt, int* __restrict__ eidx)
{
    int i = blockIdx.x * blockDim.x + threadIdx.x;
    if (i >= NS * NEP) return;
    int s = i / NEP;
    int src = rows[i];
    int dst = cols[i];
    int b = s * NN + src;
    int slot = atomicAdd(&cnt[b], 1);
    if (slot < EMAX) eidx[(size_t)b * EMAX + slot] = dst;
}

// ---------------- gather aggregation: one warp per (sector,src) --------------
// acc = sum(fp16 H rows) in fp32 (unroll-2, MLP=2); write z2 slice fp16 hi.
__global__ __launch_bounds__(256)
void gather_agg(const int* __restrict__ cnt, const int* __restrict__ eidx,
                const __half* __restrict__ H, __half* __restrict__ z2)
{
    int gw   = (blockIdx.x * blockDim.x + threadIdx.x) >> 5;
    int lane = threadIdx.x & 31;
    if (gw >= NS * NN) return;
    int s = gw / NN, src = gw - s * NN;
    int c = cnt[gw]; if (c > EMAX) c = EMAX;
    const int* lst = eidx + (size_t)gw * EMAX;
    const __half* Hs = H + (size_t)s * NN * OUTD;

    float4 acc0 = make_float4(0.f, 0.f, 0.f, 0.f);
    float4 acc1 = make_float4(0.f, 0.f, 0.f, 0.f);
    int i = 0;
    for (; i + 1 < c; i += 2) {
        const __half2* p0 = reinterpret_cast<const __half2*>(Hs + (size_t)lst[i]     * OUTD) + lane * 2;
        const __half2* p1 = reinterpret_cast<const __half2*>(Hs + (size_t)lst[i + 1] * OUTD) + lane * 2;
        __half2 a01 = p0[0], a23 = p0[1];
        __half2 b01 = p1[0], b23 = p1[1];
        acc0.x += __half2float(a01.x); acc0.y += __half2float(a01.y);
        acc0.z += __half2float(a23.x); acc0.w += __half2float(a23.y);
        acc1.x += __half2float(b01.x); acc1.y += __half2float(b01.y);
        acc1.z += __half2float(b23.x); acc1.w += __half2float(b23.y);
    }
    if (i < c) {
        const __half2* p0 = reinterpret_cast<const __half2*>(Hs + (size_t)lst[i] * OUTD) + lane * 2;
        __half2 a01 = p0[0], a23 = p0[1];
        acc0.x += __half2float(a01.x); acc0.y += __half2float(a01.y);
        acc0.z += __half2float(a23.x); acc0.w += __half2float(a23.y);
    }
    acc0.x += acc1.x; acc0.y += acc1.y; acc0.z += acc1.z; acc0.w += acc1.w;

    __half* zp = z2 + ((size_t)src * NK + 1 + s) * OUTD;
    *reinterpret_cast<__half2*>(zp + lane * 4 + 0) = __floats2half2_rn(acc0.x, acc0.y);
    *reinterpret_cast<__half2*>(zp + lane * 4 + 2) = __floats2half2_rn(acc0.z, acc0.w);
}

// ---------------- per-node interaction: one warp per node, register-resident -
__global__ __launch_bounds__(128)
void interact(const __half* __restrict__ zc, const __half* __restrict__ zd,
              const float* __restrict__ gw, const float* __restrict__ gb,
              float* __restrict__ out)
{
    __shared__ float gcs[4][NK][NK];
    __shared__ float gds[4][NK][NK];
    const int w = threadIdx.x >> 5;
    const int lane = threadIdx.x & 31;
    const int n = blockIdx.x * 4 + w;          // NN = 5000*4

    const __half2* zcn = reinterpret_cast<const __half2*>(zc + (size_t)n * NK * OUTD);
    const __half2* zdn = reinterpret_cast<const __half2*>(zd + (size_t)n * NK * OUTD);

    float a[NK][4], b[NK][4];
    #pragma unroll
    for (int r = 0; r < NK; ++r) {
        __half2 c0 = zcn[r * 64 + lane];
        __half2 c1 = zcn[r * 64 + 32 + lane];
        a[r][0] = __half2float(c0.x); a[r][1] = __half2float(c0.y);
        a[r][2] = __half2float(c1.x); a[r][3] = __half2float(c1.y);
        __half2 d0 = zdn[r * 64 + lane];
        __half2 d1 = zdn[r * 64 + 32 + lane];
        b[r][0] = __half2float(d0.x); b[r][1] = __half2float(d0.y);
        b[r][2] = __half2float(d1.x); b[r][3] = __half2float(d1.y);
    }

    #pragma unroll
    for (int k = 0; k < NK; ++k) {
        #pragma unroll
        for (int j = k; j < NK; ++j) {
            float pc = a[k][0]*a[j][0] + a[k][1]*a[j][1] + a[k][2]*a[j][2] + a[k][3]*a[j][3];
            float pd = b[k][0]*b[j][0] + b[k][1]*b[j][1] + b[k][2]*b[j][2] + b[k][3]*b[j][3];
            #pragma unroll
            for (int off = 16; off; off >>= 1) {
                pc += __shfl_xor_sync(0xffffffffu, pc, off);
                pd += __shfl_xor_sync(0xffffffffu, pd, off);
            }
            if (lane == 0) {
                gcs[w][k][j] = pc; gcs[w][j][k] = pc;
                gds[w][k][j] = pd; gds[w][j][k] = pd;
            }
        }
    }
    __syncwarp();

    if (lane < NK) {
        float row[NK]; float m = -1e30f;
        #pragma unroll
        for (int j = 0; j < NK; ++j) { row[j] = gcs[w][lane][j]; m = fmaxf(m, row[j]); }
        float ssum = 0.f;
        #pragma unroll
        for (int j = 0; j < NK; ++j) { row[j] = expf(row[j] - m); ssum += row[j]; }
        float inv = 1.f / ssum;
        #pragma unroll
        for (int j = 0; j < NK; ++j) gcs[w][lane][j] = row[j] * inv;
    } else if (lane >= 16 && lane < 16 + NK) {
        int k = lane - 16;
        float q = gds[w][k][k];
        float row[NK]; float m = -1e30f;
        #pragma unroll
        for (int j = 0; j < NK; ++j) { row[j] = q - gds[w][k][j]; m = fmaxf(m, row[j]); }
        float ssum = 0.f;
        #pragma unroll
        for (int j = 0; j < NK; ++j) { row[j] = expf(row[j] - m); ssum += row[j]; }
        float inv = 1.f / ssum;
        #pragma unroll
        for (int j = 0; j < NK; ++j) gds[w][k][j] = row[j] * inv;
    }
    __syncwarp();

    float com[NK][4], dis[NK][4];
    float gp = 0.f;
    #pragma unroll
    for (int k = 0; k < NK; ++k) {
        float ck0 = 0.f, ck1 = 0.f, ck2 = 0.f, ck3 = 0.f;
        float dk0 = 0.f, dk1 = 0.f, dk2 = 0.f, dk3 = 0.f;
        #pragma unroll
        for (int j = 0; j < NK; ++j) {
            float acv = gcs[w][k][j], adv = gds[w][k][j];
            ck0 += acv * a[j][0]; ck1 += acv * a[j][1];
            ck2 += acv * a[j][2]; ck3 += acv * a[j][3];
            dk0 += adv * b[j][0]; dk1 += adv * b[j][1];
            dk2 += adv * b[j][2]; dk3 += adv * b[j][3];
        }
        dk0 = b[k][0] - dk0; dk1 = b[k][1] - dk1;
        dk2 = b[k][2] - dk2; dk3 = b[k][3] - dk3;
        com[k][0] = ck0; com[k][1] = ck1; com[k][2] = ck2; com[k][3] = ck3;
        dis[k][0] = dk0; dis[k][1] = dk1; dis[k][2] = dk2; dis[k][3] = dk3;

        const float2 gc0 = *reinterpret_cast<const float2*>(gw + k * OUTD + 2 * lane);
        const float2 gc1 = *reinterpret_cast<const float2*>(gw + k * OUTD + 64 + 2 * lane);
        const float2 gd0 = *reinterpret_cast<const float2*>(gw + NK * OUTD + k * OUTD + 2 * lane);
        const float2 gd1 = *reinterpret_cast<const float2*>(gw + NK * OUTD + k * OUTD + 64 + 2 * lane);
        gp += ck0 * gc0.x + ck1 * gc0.y + ck2 * gc1.x + ck3 * gc1.y
            + dk0 * gd0.x + dk1 * gd0.y + dk2 * gd1.x + dk3 * gd1.y;
    }
    #pragma unroll
    for (int off = 16; off; off >>= 1)
        gp += __shfl_xor_sync(0xffffffffu, gp, off);
    const float beta = 1.f / (1.f + expf(-(gp + gb[0])));

    float* op = out + (size_t)n * (NK * OUTD);
    #pragma unroll
    for (int k = 0; k < NK; ++k) {
        float2 v0 = make_float2(beta * com[k][0] + (1.f - beta) * dis[k][0],
                                beta * com[k][1] + (1.f - beta) * dis[k][1]);
        float2 v1 = make_float2(beta * com[k][2] + (1.f - beta) * dis[k][2],
                                beta * com[k][3] + (1.f - beta) * dis[k][3]);
        *reinterpret_cast<float2*>(op + k * OUTD + 2 * lane) = v0;
        *reinterpret_cast<float2*>(op + k * OUTD + 64 + 2 * lane) = v1;
    }
}

// ---------------- launch ------------------------------------------------------
extern "C" void kernel_launch(void* const* d_in, const int* in_sizes, int n_in,
                              void* d_out, int out_size)
{
    const float* x        = (const float*)d_in[0];
    const float* W_self   = (const float*)d_in[1];
    const float* W_sect   = (const float*)d_in[2];
    const float* WC       = (const float*)d_in[3];
    const float* WD       = (const float*)d_in[4];
    const float* gate_w   = (const float*)d_in[5];
    const float* gate_b   = (const float*)d_in[6];
    const float* out_norm = (const float*)d_in[7];
    const float* in_norm  = (const float*)d_in[8];
    const int*   rows     = (const int*)d_in[9];
    const int*   cols     = (const int*)d_in[10];
    float* out = (float*)d_out;

    __half *H, *zc, *zd, *x2, *z2, *w1t, *w2t;
    int *cnt, *eidx;
    cudaGetSymbolAddress((void**)&H,    d_H);
    cudaGetSymbolAddress((void**)&zc,   d_zc);
    cudaGetSymbolAddress((void**)&zd,   d_zd);
    cudaGetSymbolAddress((void**)&x2,   d_x2);
    cudaGetSymbolAddress((void**)&z2,   d_z2);
    cudaGetSymbolAddress((void**)&w1t,  d_w1t);
    cudaGetSymbolAddress((void**)&w2t,  d_w2t);
    cudaGetSymbolAddress((void**)&cnt,  d_cnt);
    cudaGetSymbolAddress((void**)&eidx, d_eidx);

    cudaFuncSetAttribute(mma_gemm1, cudaFuncAttributeMaxDynamicSharedMemorySize, SMEM_G1);
    cudaFuncSetAttribute(mma_gemm2, cudaFuncAttributeMaxDynamicSharedMemorySize, SMEM_G2);

    // (0) convert x -> fp16 hi; also zeroes the bucket counters
    conv_x<<<(NN * IND + 255) / 256, 256>>>(x, x2, cnt);

    // (1) build per-(sector,src) edge lists
    build_lists<<<(NS * NEP + 255) / 256, 256>>>(rows, cols, cnt, eidx);

    // (2) weight conversions, right-sized grid (128 x 11 blocks)
    conv_w_all<<<dim3((IND * OUTD + 255) / 256, 11), 256>>>(W_self, W_sect, WC, WD, w1t, w2t);

    // (3) branch GEMMs, plain fp16, persistent-B   [profiled slot]
    mma_gemm1<<<dim3((NN + 127) / 128, NK), 256, SMEM_G1>>>(
        x2, w1t, z2, H, out_norm);

    // (4) gather aggregation -> z2 slices 1..8 (fp16 hi, MLP=2)
    gather_agg<<<(NS * NN * 32 + 255) / 256, 256>>>(cnt, eidx, H, z2);

    // (5) WC/WD GEMMs, plain fp16, persistent-B, pipelined (round-14 proven)
    mma_gemm2<<<dim3(2 * ((M2 + 127) / 128), 1), 256, SMEM_G2>>>(
        z2, w2t, zc, zd, in_norm);

    // (6) per-node interaction + gate, warp-per-node register-resident
    interact<<<NN / 4, 128>>>(zc, zd, gate_w, gate_b, out);
}

// round 17
// speedup vs baseline: 1.0634x; 1.0001x over previous
#include <cuda_runtime.h>
#include <cuda_fp16.h>
#include <cstdint>

// Problem constants (fixed by the dataset)
#define NN   20000   // nodes
#define IND  256     // in_dim
#define OUTD 128     // out_dim
#define NS   8       // num sectors
#define NK   9       // K = S+1
#define NEP  40000   // edges per sector
#define EMAX 64      // per-(sector,src) edge-list capacity (Poisson(2) degrees)

// ---------------- scratch (device globals; no allocations allowed) ----------
__device__ __half d_H  [(size_t)NS * NN * OUTD];            // per-sector H fp16 (41MB)
__device__ __half d_zc [(size_t)NN * NK * OUTD];            // (z*in_norm) @ WC, fp16
__device__ __half d_zd [(size_t)NN * NK * OUTD];            // (z*in_norm) @ WD, fp16
// Both GEMMs plain fp16 (hi-only operands); error budget calibrated ~5e-4.
__device__ __half d_x2 [(size_t)NN * IND];                  // [N, 256] hi
__device__ __half d_z2 [(size_t)NN * NK * OUTD];            // [N*K, 128] hi
__device__ __half d_w1t[(size_t)NK * OUTD * IND];           // [9][128,256] transposed
__device__ __half d_w2t[(size_t)2  * OUTD * OUTD];          // [2][128,128] transposed
// CSR-ish fixed-capacity edge lists, rebuilt every call
__device__ int d_cnt [(size_t)NS * NN];
__device__ int d_eidx[(size_t)NS * NN * EMAX];

// ============================ PTX helpers ====================================
__device__ __forceinline__ uint32_t smem_u32(const void* p) {
    uint32_t a;
    asm("{ .reg .u64 t; cvta.to.shared.u64 t, %1; cvt.u32.u64 %0, t; }" : "=r"(a) : "l"(p));
    return a;
}
__device__ __forceinline__ void ldmx4(uint32_t* r, uint32_t addr) {
    asm volatile("ldmatrix.sync.aligned.m8n8.x4.shared.b16 {%0,%1,%2,%3}, [%4];"
        : "=r"(r[0]), "=r"(r[1]), "=r"(r[2]), "=r"(r[3]) : "r"(addr));
}
__device__ __forceinline__ void mma16816(float* c, const uint32_t* a, uint32_t b0, uint32_t b1) {
    asm volatile("mma.sync.aligned.m16n8k16.row.col.f32.f16.f16.f32 "
        "{%0,%1,%2,%3}, {%4,%5,%6,%7}, {%8,%9}, {%0,%1,%2,%3};"
        : "+f"(c[0]), "+f"(c[1]), "+f"(c[2]), "+f"(c[3])
        : "r"(a[0]), "r"(a[1]), "r"(a[2]), "r"(a[3]), "r"(b0), "r"(b1));
}
#define CP_ASYNC16(sp, gp) \
    asm volatile("cp.async.cg.shared.global [%0], [%1], 16;" :: "r"(sp), "l"(gp))
#define CP_COMMIT() asm volatile("cp.async.commit_group;" ::: "memory")
#define CP_WAIT1()  asm volatile("cp.async.wait_group 1;" ::: "memory")
#define CP_WAIT0()  asm volatile("cp.async.wait_group 0;" ::: "memory")

// ============================ conversion kernels =============================
// x fp32 [NN, IND] -> fp16 hi only; also zeroes cnt.
__global__ __launch_bounds__(256)
void conv_x(const float* __restrict__ in, __half* __restrict__ out,
            int* __restrict__ cnt)
{
    int i = blockIdx.x * blockDim.x + threadIdx.x;
    if (i < NS * NN) cnt[i] = 0;
    if (i >= NN * IND) return;
    out[i] = __float2half_rn(in[i]);
}

// weight conversions: b 0..8 -> w1t (transposed, K=IND); b 9..10 -> w2t
// (transposed, K=OUTD). All plain fp16.
__global__ __launch_bounds__(256)
void conv_w_all(const float* __restrict__ W_self, const float* __restrict__ W_sect,
                const float* __restrict__ WC, const float* __restrict__ WD,
                __half* __restrict__ w1t, __half* __restrict__ w2t)
{
    int b = blockIdx.y;
    int i = blockIdx.x * blockDim.x + threadIdx.x;
    if (b < 9) {
        const float* W = (b == 0) ? W_self : W_sect + (size_t)(b - 1) * IND * OUTD;
        __half* ob = w1t + (size_t)b * OUTD * IND;
        if (i >= IND * OUTD) return;
        int k = i / OUTD, n = i - k * OUTD;
        ob[(size_t)n * IND + k] = __float2half_rn(W[i]);
    } else {
        const float* W = (b == 9) ? WC : WD;
        __half* ob = w2t + (size_t)(b - 9) * OUTD * OUTD;
        if (i >= OUTD * OUTD) return;
        int k = i / OUTD, n = i - k * OUTD;
        ob[(size_t)n * OUTD + k] = __float2half_rn(W[i]);
    }
}

// ============================ shared GEMM pieces =============================
#define SROW 144                      // smem row pitch bytes (64 fp16 cols + pad)
#define ATILE (128 * SROW)            // 18432 B
#define SMEM_G1 (6 * ATILE)           // mma1: 4 B-chunks + 2 A-buffers
#define SMEM_G2 (6 * ATILE)           // mma2: 4 B-chunks (WC+WD) + 2 A-chunks

// warp-level MMA on one 64-col chunk: warp tile 64(M) x 32(N), 4 k16 steps.
__device__ __forceinline__ void chunk_mma(uint32_t sAb, uint32_t sBb,
                                          int warpM, int warpN, int lane,
                                          float acc[4][4][4])
{
    #pragma unroll
    for (int ks = 0; ks < 4; ++ks) {
        const uint32_t colOff = (ks * 16 + (lane >> 4) * 8) * 2;
        uint32_t a[4][4];
        #pragma unroll
        for (int mt = 0; mt < 4; ++mt)
            ldmx4(a[mt], sAb + (warpM * 64 + mt * 16 + (lane & 15)) * SROW + colOff);
        uint32_t b[2][4];
        #pragma unroll
        for (int nt2 = 0; nt2 < 2; ++nt2)
            ldmx4(b[nt2], sBb + (warpN * 32 + nt2 * 16 + (lane & 15)) * SROW + colOff);
        #pragma unroll
        for (int mt = 0; mt < 4; ++mt)
            #pragma unroll
            for (int nt2 = 0; nt2 < 2; ++nt2) {
                mma16816(acc[mt][nt2 * 2 + 0], a[mt], b[nt2][0], b[nt2][2]);
                mma16816(acc[mt][nt2 * 2 + 1], a[mt], b[nt2][1], b[nt2][3]);
            }
    }
}

// ============================ GEMM 1: branch GEMM ============================
// C[M,128] = x_hi[M,256] @ w_hi[128,256]^T, plain fp16. 256 thr, 8 warps 2x4.
// B persistent in smem (4 k-chunks, 64KB); A streams through 2 buffers.
// grid (tiles, 9). branch 0 -> z2 slice 0 (fp16 hi); 1..8 -> H fp16 * out_norm.
__global__ __launch_bounds__(256, 2)
void mma_gemm1(const __half* __restrict__ A2, const __half* __restrict__ Bbase,
               __half* __restrict__ z2out, __half* __restrict__ Hout,
               const float* __restrict__ out_norm)
{
    extern __shared__ __align__(16) char smem[];
    char* sB = smem;                    // B chunks [0..3]
    char* sA = smem + 4 * ATILE;        // A buffers [0..1]

    const int tid = threadIdx.x;
    const int wid = tid >> 5, lane = tid & 31;
    const int warpM = wid & 1, warpN = wid >> 1;
    const int branch = blockIdx.y;
    const int rowBase = blockIdx.x * 128;
    const int lda = IND;                // 256
    const __half* B2 = Bbase + (size_t)branch * OUTD * lda;
    const uint32_t sB_u = smem_u32(sB);
    const uint32_t sA_u = smem_u32(sA);
    float acc[4][4][4] = {};

    auto loadA = [&](int c, int buf) {
        char* dst = sA + buf * ATILE;
        int k0 = c * 64;
        #pragma unroll
        for (int i = 0; i < 4; ++i) {
            int idx = tid + i * 256;
            int r = idx >> 3, c16 = idx & 7;
            int grow = rowBase + r; if (grow > NN - 1) grow = NN - 1;
            CP_ASYNC16(smem_u32(dst + r * SROW + c16 * 16),
                       A2 + (size_t)grow * lda + k0 + c16 * 8);
        }
    };

    // persistent B: 4 chunk-tiles
    #pragma unroll
    for (int ch = 0; ch < 4; ++ch) {
        char* dst = sB + ch * ATILE;
        #pragma unroll
        for (int i = 0; i < 4; ++i) {
            int idx = tid + i * 256;
            int r = idx >> 3, c16 = idx & 7;
            CP_ASYNC16(smem_u32(dst + r * SROW + c16 * 16),
                       B2 + (size_t)r * lda + ch * 64 + c16 * 8);
        }
    }
    loadA(0, 0); CP_COMMIT();           // G0 = B + A0
    loadA(1, 1); CP_COMMIT();           // G1 = A1

    #pragma unroll
    for (int c = 0; c < 4; ++c) {
        if (c + 1 < 4) CP_WAIT1(); else CP_WAIT0();
        __syncthreads();                // A[c%2] + (c==0: all B) ready
        chunk_mma(sA_u + (c & 1) * ATILE, sB_u + c * ATILE, warpM, warpN, lane, acc);
        if (c + 2 < 4) {
            __syncthreads();            // everyone done with buffer (c%2)
            loadA(c + 2, c & 1); CP_COMMIT();
        }
    }

    const int g = lane >> 2, t4 = lane & 3;
    #pragma unroll
    for (int mt = 0; mt < 4; ++mt) {
        int row0 = rowBase + warpM * 64 + mt * 16 + g;
        int row1 = row0 + 8;
        if (branch == 0) {
            #pragma unroll
            for (int nt = 0; nt < 4; ++nt) {
                int col = warpN * 32 + nt * 8 + 2 * t4;
                if (row0 < NN) {
                    __half2 v = __floats2half2_rn(acc[mt][nt][0], acc[mt][nt][1]);
                    *reinterpret_cast<__half2*>(z2out + (size_t)row0 * NK * OUTD + col) = v;
                }
                if (row1 < NN) {
                    __half2 v = __floats2half2_rn(acc[mt][nt][2], acc[mt][nt][3]);
                    *reinterpret_cast<__half2*>(z2out + (size_t)row1 * NK * OUTD + col) = v;
                }
            }
        } else {
            __half* C = Hout + (size_t)(branch - 1) * NN * OUTD;
            float s0 = (row0 < NN) ? out_norm[row0] : 0.f;
            float s1 = (row1 < NN) ? out_norm[row1] : 0.f;
            #pragma unroll
            for (int nt = 0; nt < 4; ++nt) {
                int col = warpN * 32 + nt * 8 + 2 * t4;
                if (row0 < NN) {
                    __half2 v = __floats2half2_rn(acc[mt][nt][0] * s0, acc[mt][nt][1] * s0);
                    *reinterpret_cast<__half2*>(C + (size_t)row0 * OUTD + col) = v;
                }
                if (row1 < NN) {
                    __half2 v = __floats2half2_rn(acc[mt][nt][2] * s1, acc[mt][nt][3] * s1);
                    *reinterpret_cast<__half2*>(C + (size_t)row1 * OUTD + col) = v;
                }
            }
        }
    }
}

// ============================ GEMM 2: dual-branch WC+WD =====================
// One 256-thread CTA computes BOTH zc and zd for its 128 rows. Both weight
// matrices persistent in smem (4 chunks); A loaded ONCE (2 chunks), reused
// across the two branch passes; acc registers reused (re-zeroed). occ 2.
#define M2 (NN * NK)
__global__ __launch_bounds__(256, 2)
void mma_gemm2(const __half* __restrict__ A2, const __half* __restrict__ Bbase,
               __half* __restrict__ zc, __half* __restrict__ zd,
               const float* __restrict__ in_norm)
{
    extern __shared__ __align__(16) char smem[];
    char* sB = smem;                    // [WC k0, WC k1, WD k0, WD k1]
    char* sA = smem + 4 * ATILE;        // A chunks [k0, k1]

    const int tid = threadIdx.x;
    const int wid = tid >> 5, lane = tid & 31;
    const int warpM = wid & 1, warpN = wid >> 1;
    const int rowBase = blockIdx.x * 128;
    const int lda = OUTD;               // 128
    const uint32_t sB_u = smem_u32(sB);
    const uint32_t sA_u = smem_u32(sA);

    // persistent B: both branches' 2 k-chunks each
    #pragma unroll
    for (int ch = 0; ch < 4; ++ch) {
        int bh = ch >> 1, kc = ch & 1;
        const __half* Bsrc = Bbase + (size_t)bh * OUTD * OUTD;
        char* dst = sB + ch * ATILE;
        #pragma unroll
        for (int i = 0; i < 4; ++i) {
            int idx = tid + i * 256;
            int r = idx >> 3, c16 = idx & 7;
            CP_ASYNC16(smem_u32(dst + r * SROW + c16 * 16),
                       Bsrc + (size_t)r * lda + kc * 64 + c16 * 8);
        }
    }
    // A chunk 0 in group 0 (with B), chunk 1 in group 1
    #pragma unroll
    for (int kc = 0; kc < 2; ++kc) {
        char* dst = sA + kc * ATILE;
        #pragma unroll
        for (int i = 0; i < 4; ++i) {
            int idx = tid + i * 256;
            int r = idx >> 3, c16 = idx & 7;
            int grow = rowBase + r; if (grow > M2 - 1) grow = M2 - 1;
            CP_ASYNC16(smem_u32(dst + r * SROW + c16 * 16),
                       A2 + (size_t)grow * lda + kc * 64 + c16 * 8);
        }
        CP_COMMIT();                    // G0 = B + A0 ; G1 = A1
    }

    const int g = lane >> 2, t4 = lane & 3;
    #pragma unroll
    for (int br = 0; br < 2; ++br) {
        float acc[4][4][4] = {};
        #pragma unroll
        for (int c = 0; c < 2; ++c) {
            if (br == 0) {
                if (c == 0) CP_WAIT1(); else CP_WAIT0();
                __syncthreads();
            }
            chunk_mma(sA_u + c * ATILE, sB_u + (br * 2 + c) * ATILE,
                      warpM, warpN, lane, acc);
        }
        __half* C = br ? zd : zc;
        #pragma unroll
        for (int mt = 0; mt < 4; ++mt) {
            int row0 = rowBase + warpM * 64 + mt * 16 + g;
            int row1 = row0 + 8;
            float s0 = (row0 < M2) ? in_norm[row0 / NK] : 0.f;
            float s1 = (row1 < M2) ? in_norm[row1 / NK] : 0.f;
            #pragma unroll
            for (int nt = 0; nt < 4; ++nt) {
                int col = warpN * 32 + nt * 8 + 2 * t4;
                if (row0 < M2) {
                    __half2 v = __floats2half2_rn(acc[mt][nt][0] * s0, acc[mt][nt][1] * s0);
                    *reinterpret_cast<__half2*>(C + (size_t)row0 * OUTD + col) = v;
                }
                if (row1 < M2) {
                    __half2 v = __floats2half2_rn(acc[mt][nt][2] * s1, acc[mt][nt][3] * s1);
                    *reinterpret_cast<__half2*>(C + (size_t)row1 * OUTD + col) = v;
                }
            }
        }
    }
}

// ---------------- edge-list build: bucket (sector,src) <- dst ----------------
__global__ __launch_bounds__(256)
void build_lists(const int* __restrict__ rows, const int* __restrict__ cols,
                 int* __restrict__ cnt, int* __restrict__ eidx)
{
    int i = blockIdx.x * blockDim.x + threadIdx.x;
    if (i >= NS * NEP) return;
    int s = i / NEP;
    int src = rows[i];
    int dst = cols[i];
    int b = s * NN + src;
    int slot = atomicAdd(&cnt[b], 1);
    if (slot < EMAX) eidx[(size_t)b * EMAX + slot] = dst;
}

// ---------------- gather aggregation: one warp per (sector,src) --------------
// acc = sum(fp16 H rows) in fp32 (unroll-2, MLP=2); write z2 slice fp16 hi.
__global__ __launch_bounds__(256)
void gather_agg(const int* __restrict__ cnt, const int* __restrict__ eidx,
                const __half* __restrict__ H, __half* __restrict__ z2)
{
    int gw   = (blockIdx.x * blockDim.x + threadIdx.x) >> 5;
    int lane = threadIdx.x & 31;
    if (gw >= NS * NN) return;
    int s = gw / NN, src = gw - s * NN;
    int c = cnt[gw]; if (c > EMAX) c = EMAX;
    const int* lst = eidx + (size_t)gw * EMAX;
    const __half* Hs = H + (size_t)s * NN * OUTD;

    float4 acc0 = make_float4(0.f, 0.f, 0.f, 0.f);
    float4 acc1 = make_float4(0.f, 0.f, 0.f, 0.f);
    int i = 0;
    for (; i + 1 < c; i += 2) {
        const __half2* p0 = reinterpret_cast<const __half2*>(Hs + (size_t)lst[i]     * OUTD) + lane * 2;
        const __half2* p1 = reinterpret_cast<const __half2*>(Hs + (size_t)lst[i + 1] * OUTD) + lane * 2;
        __half2 a01 = p0[0], a23 = p0[1];
        __half2 b01 = p1[0], b23 = p1[1];
        acc0.x += __half2float(a01.x); acc0.y += __half2float(a01.y);
        acc0.z += __half2float(a23.x); acc0.w += __half2float(a23.y);
        acc1.x += __half2float(b01.x); acc1.y += __half2float(b01.y);
        acc1.z += __half2float(b23.x); acc1.w += __half2float(b23.y);
    }
    if (i < c) {
        const __half2* p0 = reinterpret_cast<const __half2*>(Hs + (size_t)lst[i] * OUTD) + lane * 2;
        __half2 a01 = p0[0], a23 = p0[1];
        acc0.x += __half2float(a01.x); acc0.y += __half2float(a01.y);
        acc0.z += __half2float(a23.x); acc0.w += __half2float(a23.y);
    }
    acc0.x += acc1.x; acc0.y += acc1.y; acc0.z += acc1.z; acc0.w += acc1.w;

    __half* zp = z2 + ((size_t)src * NK + 1 + s) * OUTD;
    *reinterpret_cast<__half2*>(zp + lane * 4 + 0) = __floats2half2_rn(acc0.x, acc0.y);
    *reinterpret_cast<__half2*>(zp + lane * 4 + 2) = __floats2half2_rn(acc0.z, acc0.w);
}

// ---------------- per-node interaction: one warp per node, register-resident -
__global__ __launch_bounds__(128)
void interact(const __half* __restrict__ zc, const __half* __restrict__ zd,
              const float* __restrict__ gw, const float* __restrict__ gb,
              float* __restrict__ out)
{
    __shared__ float gcs[4][NK][NK];
    __shared__ float gds[4][NK][NK];
    const int w = threadIdx.x >> 5;
    const int lane = threadIdx.x & 31;
    const int n = blockIdx.x * 4 + w;          // NN = 5000*4

    const __half2* zcn = reinterpret_cast<const __half2*>(zc + (size_t)n * NK * OUTD);
    const __half2* zdn = reinterpret_cast<const __half2*>(zd + (size_t)n * NK * OUTD);

    float a[NK][4], b[NK][4];
    #pragma unroll
    for (int r = 0; r < NK; ++r) {
        __half2 c0 = zcn[r * 64 + lane];
        __half2 c1 = zcn[r * 64 + 32 + lane];
        a[r][0] = __half2float(c0.x); a[r][1] = __half2float(c0.y);
        a[r][2] = __half2float(c1.x); a[r][3] = __half2float(c1.y);
        __half2 d0 = zdn[r * 64 + lane];
        __half2 d1 = zdn[r * 64 + 32 + lane];
        b[r][0] = __half2float(d0.x); b[r][1] = __half2float(d0.y);
        b[r][2] = __half2float(d1.x); b[r][3] = __half2float(d1.y);
    }

    #pragma unroll
    for (int k = 0; k < NK; ++k) {
        #pragma unroll
        for (int j = k; j < NK; ++j) {
            float pc = a[k][0]*a[j][0] + a[k][1]*a[j][1] + a[k][2]*a[j][2] + a[k][3]*a[j][3];
            float pd = b[k][0]*b[j][0] + b[k][1]*b[j][1] + b[k][2]*b[j][2] + b[k][3]*b[j][3];
            #pragma unroll
            for (int off = 16; off; off >>= 1) {
                pc += __shfl_xor_sync(0xffffffffu, pc, off);
                pd += __shfl_xor_sync(0xffffffffu, pd, off);
            }
            if (lane == 0) {
                gcs[w][k][j] = pc; gcs[w][j][k] = pc;
                gds[w][k][j] = pd; gds[w][j][k] = pd;
            }
        }
    }
    __syncwarp();

    if (lane < NK) {
        float row[NK]; float m = -1e30f;
        #pragma unroll
        for (int j = 0; j < NK; ++j) { row[j] = gcs[w][lane][j]; m = fmaxf(m, row[j]); }
        float ssum = 0.f;
        #pragma unroll
        for (int j = 0; j < NK; ++j) { row[j] = expf(row[j] - m); ssum += row[j]; }
        float inv = 1.f / ssum;
        #pragma unroll
        for (int j = 0; j < NK; ++j) gcs[w][lane][j] = row[j] * inv;
    } else if (lane >= 16 && lane < 16 + NK) {
        int k = lane - 16;
        float q = gds[w][k][k];
        float row[NK]; float m = -1e30f;
        #pragma unroll
        for (int j = 0; j < NK; ++j) { row[j] = q - gds[w][k][j]; m = fmaxf(m, row[j]); }
        float ssum = 0.f;
        #pragma unroll
        for (int j = 0; j < NK; ++j) { row[j] = expf(row[j] - m); ssum += row[j]; }
        float inv = 1.f / ssum;
        #pragma unroll
        for (int j = 0; j < NK; ++j) gds[w][k][j] = row[j] * inv;
    }
    __syncwarp();

    float com[NK][4], dis[NK][4];
    float gp = 0.f;
    #pragma unroll
    for (int k = 0; k < NK; ++k) {
        float ck0 = 0.f, ck1 = 0.f, ck2 = 0.f, ck3 = 0.f;
        float dk0 = 0.f, dk1 = 0.f, dk2 = 0.f, dk3 = 0.f;
        #pragma unroll
        for (int j = 0; j < NK; ++j) {
            float acv = gcs[w][k][j], adv = gds[w][k][j];
            ck0 += acv * a[j][0]; ck1 += acv * a[j][1];
            ck2 += acv * a[j][2]; ck3 += acv * a[j][3];
            dk0 += adv * b[j][0]; dk1 += adv * b[j][1];
            dk2 += adv * b[j][2]; dk3 += adv * b[j][3];
        }
        dk0 = b[k][0] - dk0; dk1 = b[k][1] - dk1;
        dk2 = b[k][2] - dk2; dk3 = b[k][3] - dk3;
        com[k][0] = ck0; com[k][1] = ck1; com[k][2] = ck2; com[k][3] = ck3;
        dis[k][0] = dk0; dis[k][1] = dk1; dis[k][2] = dk2; dis[k][3] = dk3;

        const float2 gc0 = *reinterpret_cast<const float2*>(gw + k * OUTD + 2 * lane);
        const float2 gc1 = *reinterpret_cast<const float2*>(gw + k * OUTD + 64 + 2 * lane);
        const float2 gd0 = *reinterpret_cast<const float2*>(gw + NK * OUTD + k * OUTD + 2 * lane);
        const float2 gd1 = *reinterpret_cast<const float2*>(gw + NK * OUTD + k * OUTD + 64 + 2 * lane);
        gp += ck0 * gc0.x + ck1 * gc0.y + ck2 * gc1.x + ck3 * gc1.y
            + dk0 * gd0.x + dk1 * gd0.y + dk2 * gd1.x + dk3 * gd1.y;
    }
    #pragma unroll
    for (int off = 16; off; off >>= 1)
        gp += __shfl_xor_sync(0xffffffffu, gp, off);
    const float beta = 1.f / (1.f + expf(-(gp + gb[0])));

    float* op = out + (size_t)n * (NK * OUTD);
    #pragma unroll
    for (int k = 0; k < NK; ++k) {
        float2 v0 = make_float2(beta * com[k][0] + (1.f - beta) * dis[k][0],
                                beta * com[k][1] + (1.f - beta) * dis[k][1]);
        float2 v1 = make_float2(beta * com[k][2] + (1.f - beta) * dis[k][2],
                                beta * com[k][3] + (1.f - beta) * dis[k][3]);
        *reinterpret_cast<float2*>(op + k * OUTD + 2 * lane) = v0;
        *reinterpret_cast<float2*>(op + k * OUTD + 64 + 2 * lane) = v1;
    }
}

// ---------------- launch ------------------------------------------------------
extern "C" void kernel_launch(void* const* d_in, const int* in_sizes, int n_in,
                              void* d_out, int out_size)
{
    const float* x        = (const float*)d_in[0];
    const float* W_self   = (const float*)d_in[1];
    const float* W_sect   = (const float*)d_in[2];
    const float* WC       = (const float*)d_in[3];
    const float* WD       = (const float*)d_in[4];
    const float* gate_w   = (const float*)d_in[5];
    const float* gate_b   = (const float*)d_in[6];
    const float* out_norm = (const float*)d_in[7];
    const float* in_norm  = (const float*)d_in[8];
    const int*   rows     = (const int*)d_in[9];
    const int*   cols     = (const int*)d_in[10];
    float* out = (float*)d_out;

    __half *H, *zc, *zd, *x2, *z2, *w1t, *w2t;
    int *cnt, *eidx;
    cudaGetSymbolAddress((void**)&H,    d_H);
    cudaGetSymbolAddress((void**)&zc,   d_zc);
    cudaGetSymbolAddress((void**)&zd,   d_zd);
    cudaGetSymbolAddress((void**)&x2,   d_x2);
    cudaGetSymbolAddress((void**)&z2,   d_z2);
    cudaGetSymbolAddress((void**)&w1t,  d_w1t);
    cudaGetSymbolAddress((void**)&w2t,  d_w2t);
    cudaGetSymbolAddress((void**)&cnt,  d_cnt);
    cudaGetSymbolAddress((void**)&eidx, d_eidx);

    cudaFuncSetAttribute(mma_gemm1, cudaFuncAttributeMaxDynamicSharedMemorySize, SMEM_G1);
    cudaFuncSetAttribute(mma_gemm2, cudaFuncAttributeMaxDynamicSharedMemorySize, SMEM_G2);

    // (0) convert x -> fp16 hi; also zeroes the bucket counters
    conv_x<<<(NN * IND + 255) / 256, 256>>>(x, x2, cnt);

    // (1) build per-(sector,src) edge lists
    build_lists<<<(NS * NEP + 255) / 256, 256>>>(rows, cols, cnt, eidx);

    // (2) weight conversions, right-sized grid (128 x 11 blocks)
    conv_w_all<<<dim3((IND * OUTD + 255) / 256, 11), 256>>>(W_self, W_sect, WC, WD, w1t, w2t);

    // (3) branch GEMMs, plain fp16, persistent-B   [profiled slot]
    mma_gemm1<<<dim3((NN + 127) / 128, NK), 256, SMEM_G1>>>(
        x2, w1t, z2, H, out_norm);

    // (4) gather aggregation -> z2 slices 1..8 (fp16 hi, MLP=2)
    gather_agg<<<(NS * NN * 32 + 255) / 256, 256>>>(cnt, eidx, H, z2);

    // (5) dual-branch WC+WD GEMM: A read once, occ 2, grid halved
    mma_gemm2<<<(M2 + 127) / 128, 256, SMEM_G2>>>(
        z2, w2t, zc, zd, in_norm);

    // (6) per-node interaction + gate, warp-per-node register-resident
    interact<<<NN / 4, 128>>>(zc, zd, gate_w, gate_b, out);
}